// round 8
// baseline (speedup 1.0000x reference)
#include <cuda_runtime.h>
#include <cuda_bf16.h>

#define KBINS 16
#define MAGIC 8388608.0f   // 2^23
#define VPT 8              // float4s per thread (full blocks)
#define TPB 256
#define TILE4 (VPT * TPB)  // 2048 float4s = 32KB per CTA

// Branchless LCQ quantize-dequantize. Per element:
//   f   = min(|x| * (16/alpha), 15.9999990)    // in [0,16); ~16 <=> high region
//   bi  = lowbits(fadd_rd(f, 2^23)) & 15       // == floor(f), bit-exact
//   y15 = fma(tab[bi].x, f, tab[bi].y)         // tab = {gx, s*beta - gx*bi}
//   q   = lowbits(fadd_rn(y15, 2^23)) & 15     // == rint(y15), bit-exact
//   out = copysign(lutA[q], x)                 // lutA[15] = alpha (high region)
//
// Cache policy: DEFAULT loads (input ~134MB nearly fits 126MB L2 -> retain
// across graph replays) + evict-first .cs stores (output never re-read;
// keep it from evicting the input).

__device__ __forceinline__ float lcq_elem(float xx, float c,
                                          const float2* __restrict__ tab,
                                          const float* __restrict__ lutA) {
    float f = fminf(fabsf(xx) * c, 15.9999990f);
    int bi = __float_as_int(__fadd_rd(f, MAGIC)) & 15;   // floor(f)
    float2 gd = tab[bi];                                 // {gx, d}
    float y15 = fmaf(gd.x, f, gd.y);
    int q = __float_as_int(__fadd_rn(y15, MAGIC)) & 15;  // rint(y15)
    return copysignf(lutA[q], xx);
}

__device__ __forceinline__ void lcq_vec4(float4& v, float c,
                                         const float2* __restrict__ tab,
                                         const float* __restrict__ lutA) {
    v.x = lcq_elem(v.x, c, tab, lutA);
    v.y = lcq_elem(v.y, c, tab, lutA);
    v.z = lcq_elem(v.z, c, tab, lutA);
    v.w = lcq_elem(v.w, c, tab, lutA);
}

__global__ void __launch_bounds__(TPB, 5)
lcq_kernel(const float* __restrict__ x,
           const float* __restrict__ thr,
           const float* __restrict__ theta,
           const float* __restrict__ dst,
           const int* __restrict__ qp,
           float* __restrict__ out,
           int nfull_blocks,   // blocks with a complete TILE4 tile
           int n4,             // total float4 count
           int n) {            // total element count
    __shared__ float2 s_tab[KBINS];    // {gx, s*beta - gx*bi}
    __shared__ float  s_lutA[KBINS];   // alpha * expand(q/s)
    __shared__ float  s_c;             // 16/alpha

    if (threadIdx.x == 0) {
        float th[KBINS];
        float m = theta[0];
        #pragma unroll
        for (int i = 0; i < KBINS; i++) { th[i] = theta[i]; m = fmaxf(m, th[i]); }
        float sum = 0.0f;
        #pragma unroll
        for (int i = 0; i < KBINS; i++) { th[i] = expf(th[i] - m); sum += th[i]; }
        float inv = 1.0f / sum;

        float gamma[KBINS], beta[KBINS];
        float c = 0.0f;
        #pragma unroll
        for (int i = 0; i < KBINS; i++) {
            float t = th[i] * inv;
            gamma[i] = t * (float)KBINS;
            beta[i]  = c;
            c += t;
        }

        float s = (float)qp[0];        // Qp (=15)
        float alpha = thr[0];

        #pragma unroll
        for (int i = 0; i < KBINS; i++) {
            float gx = s * gamma[i] * 0.0625f;
            s_tab[i] = make_float2(gx, fmaf(-gx, (float)i, s * beta[i]));
        }

        // expand LUT: idx = last j with beta[j] <= t
        #pragma unroll
        for (int q = 0; q < KBINS; q++) {
            float t = (float)q / s;
            int idx = 0;
            #pragma unroll
            for (int j = 0; j < KBINS; j++)
                if (beta[j] <= t) idx = j;
            s_lutA[q] = alpha * ((t - beta[idx]) / gamma[idx] + dst[idx]);
        }
        s_c = 16.0f / alpha;
    }
    __syncthreads();

    const float c = s_c;
    const float4* __restrict__ x4 = (const float4*)x;
    float4* __restrict__ o4 = (float4*)out;

    int b = blockIdx.x;
    if (b < nfull_blocks) {
        // Full tile: 8 LDG.128 front-batched (MLP=8), default cache policy
        // (L2-retain input), then compute+store each in place.
        int base = b * TILE4 + (int)threadIdx.x;
        float4 v0 = x4[base];
        float4 v1 = x4[base + TPB];
        float4 v2 = x4[base + 2 * TPB];
        float4 v3 = x4[base + 3 * TPB];
        float4 v4 = x4[base + 4 * TPB];
        float4 v5 = x4[base + 5 * TPB];
        float4 v6 = x4[base + 6 * TPB];
        float4 v7 = x4[base + 7 * TPB];

        lcq_vec4(v0, c, s_tab, s_lutA);  __stcs(&o4[base],           v0);
        lcq_vec4(v1, c, s_tab, s_lutA);  __stcs(&o4[base + TPB],     v1);
        lcq_vec4(v2, c, s_tab, s_lutA);  __stcs(&o4[base + 2 * TPB], v2);
        lcq_vec4(v3, c, s_tab, s_lutA);  __stcs(&o4[base + 3 * TPB], v3);
        lcq_vec4(v4, c, s_tab, s_lutA);  __stcs(&o4[base + 4 * TPB], v4);
        lcq_vec4(v5, c, s_tab, s_lutA);  __stcs(&o4[base + 5 * TPB], v5);
        lcq_vec4(v6, c, s_tab, s_lutA);  __stcs(&o4[base + 6 * TPB], v6);
        lcq_vec4(v7, c, s_tab, s_lutA);  __stcs(&o4[base + 7 * TPB], v7);
    } else {
        // Remainder block: guarded float4 loop + scalar tail.
        for (int i = nfull_blocks * TILE4 + (int)threadIdx.x; i < n4; i += TPB) {
            float4 v = x4[i];
            lcq_vec4(v, c, s_tab, s_lutA);
            __stcs(&o4[i], v);
        }
        for (int j = (n4 << 2) + (int)threadIdx.x; j < n; j += TPB) {
            out[j] = lcq_elem(x[j], c, s_tab, s_lutA);
        }
    }
}

extern "C" void kernel_launch(void* const* d_in, const int* in_sizes, int n_in,
                              void* d_out, int out_size) {
    // metadata order: x, threshold, theta, dst, Qn, Qp, num_elements
    const float* x     = (const float*)d_in[0];
    const float* thr   = (const float*)d_in[1];
    const float* theta = (const float*)d_in[2];
    const float* dst   = (const float*)d_in[3];
    const int*   qp    = (const int*)d_in[5];
    float* out = (float*)d_out;

    int n  = in_sizes[0];
    int n4 = n >> 2;
    int nfull_blocks = n4 / TILE4;
    int has_tail = (n4 - nfull_blocks * TILE4) != 0 || (n & 3) != 0;
    int blocks = nfull_blocks + (has_tail ? 1 : 0);
    if (blocks < 1) blocks = 1;

    lcq_kernel<<<blocks, TPB>>>(x, thr, theta, dst, qp, out,
                                nfull_blocks, n4, n);
}

// round 9
// speedup vs baseline: 1.0821x; 1.0821x over previous
#include <cuda_runtime.h>
#include <cstdint>

#define KBINS 16
#define MAGIC 8388608.0f      // 2^23
#define TPB 256
#define STAGES 5
#define TILE_ELEMS 2048       // 8KB per tile
#define TILE_BYTES (TILE_ELEMS * 4)

// ---- mbarrier / bulk-async helpers ----------------------------------------
__device__ __forceinline__ uint32_t smem_u32(const void* p) {
    return (uint32_t)__cvta_generic_to_shared(p);
}
__device__ __forceinline__ void mbar_init(uint32_t a, uint32_t cnt) {
    asm volatile("mbarrier.init.shared.b64 [%0], %1;" :: "r"(a), "r"(cnt) : "memory");
}
__device__ __forceinline__ void mbar_expect_tx(uint32_t a, uint32_t bytes) {
    asm volatile("mbarrier.arrive.expect_tx.shared.b64 _, [%0], %1;"
                 :: "r"(a), "r"(bytes) : "memory");
}
__device__ __forceinline__ void mbar_arrive(uint32_t a) {
    asm volatile("mbarrier.arrive.shared.b64 _, [%0];" :: "r"(a) : "memory");
}
__device__ __forceinline__ void mbar_wait(uint32_t a, uint32_t ph) {
    uint32_t done;
    asm volatile("{\n\t.reg .pred p;\n\t"
                 "mbarrier.try_wait.parity.acquire.cta.shared::cta.b64 p, [%1], %2;\n\t"
                 "selp.b32 %0, 1, 0, p;\n\t}"
                 : "=r"(done) : "r"(a), "r"(ph) : "memory");
    while (!done) {
        asm volatile("{\n\t.reg .pred p;\n\t"
                     "mbarrier.try_wait.parity.acquire.cta.shared::cta.b64 p, [%1], %2, 0x989680;\n\t"
                     "selp.b32 %0, 1, 0, p;\n\t}"
                     : "=r"(done) : "r"(a), "r"(ph) : "memory");
    }
}
__device__ __forceinline__ void bulk_g2s(uint32_t dst, const void* src,
                                         uint32_t bytes, uint32_t mbar) {
    asm volatile("cp.async.bulk.shared::cluster.global.mbarrier::complete_tx::bytes "
                 "[%0], [%1], %2, [%3];"
                 :: "r"(dst), "l"(src), "r"(bytes), "r"(mbar) : "memory");
}

// ---- LCQ per-element math (bit-exact magic-number rounding) ----------------
__device__ __forceinline__ float lcq_elem(float xx, float c,
                                          const float2* __restrict__ tab,
                                          const float* __restrict__ lutA) {
    float f = fminf(fabsf(xx) * c, 15.9999990f);
    int bi = __float_as_int(__fadd_rd(f, MAGIC)) & 15;   // floor(f)
    float2 gd = tab[bi];                                 // {gx, d}
    float y15 = fmaf(gd.x, f, gd.y);
    int q = __float_as_int(__fadd_rn(y15, MAGIC)) & 15;  // rint(y15)
    return copysignf(lutA[q], xx);
}
__device__ __forceinline__ void lcq_vec4(float4& v, float c,
                                         const float2* __restrict__ tab,
                                         const float* __restrict__ lutA) {
    v.x = lcq_elem(v.x, c, tab, lutA);
    v.y = lcq_elem(v.y, c, tab, lutA);
    v.z = lcq_elem(v.z, c, tab, lutA);
    v.w = lcq_elem(v.w, c, tab, lutA);
}

__global__ void __launch_bounds__(TPB)
lcq_kernel(const float* __restrict__ x,
           const float* __restrict__ thr,
           const float* __restrict__ theta,
           const float* __restrict__ dst,
           const int* __restrict__ qp,
           float* __restrict__ out,
           int ntiles, int n) {
    __shared__ __align__(128) float s_buf[STAGES][TILE_ELEMS];  // 40KB ring
    __shared__ uint64_t s_full[STAGES];
    __shared__ uint64_t s_empty[STAGES];
    __shared__ float2 s_tab[KBINS];
    __shared__ float  s_lutA[KBINS];
    __shared__ float  s_c;

    const int tid = threadIdx.x;

    if (tid == 0) {
        // ---- constant tables (softmax/cumsum/affine folds, expand LUT) ----
        float th[KBINS];
        float m = theta[0];
        #pragma unroll
        for (int i = 0; i < KBINS; i++) { th[i] = theta[i]; m = fmaxf(m, th[i]); }
        float sum = 0.0f;
        #pragma unroll
        for (int i = 0; i < KBINS; i++) { th[i] = expf(th[i] - m); sum += th[i]; }
        float inv = 1.0f / sum;
        float gamma[KBINS], beta[KBINS];
        float acc = 0.0f;
        #pragma unroll
        for (int i = 0; i < KBINS; i++) {
            float t = th[i] * inv;
            gamma[i] = t * (float)KBINS;
            beta[i]  = acc;
            acc += t;
        }
        float s = (float)qp[0];
        float alpha = thr[0];
        #pragma unroll
        for (int i = 0; i < KBINS; i++) {
            float gx = s * gamma[i] * 0.0625f;
            s_tab[i] = make_float2(gx, fmaf(-gx, (float)i, s * beta[i]));
        }
        #pragma unroll
        for (int q = 0; q < KBINS; q++) {
            float t = (float)q / s;
            int idx = 0;
            #pragma unroll
            for (int j = 0; j < KBINS; j++)
                if (beta[j] <= t) idx = j;
            s_lutA[q] = alpha * ((t - beta[idx]) / gamma[idx] + dst[idx]);
        }
        s_c = 16.0f / alpha;

        // ---- pipeline barriers ----
        #pragma unroll
        for (int sg = 0; sg < STAGES; sg++) {
            mbar_init(smem_u32(&s_full[sg]), 1);      // tx-tracked
            mbar_init(smem_u32(&s_empty[sg]), TPB);   // all threads arrive
        }
    }
    __syncthreads();

    const float c = s_c;

    // tiles owned by this CTA: t = blockIdx.x + k*gridDim.x
    int my_count = 0;
    if (blockIdx.x < ntiles)
        my_count = (ntiles - blockIdx.x + gridDim.x - 1) / gridDim.x;

    // ---- prologue: fill the ring ----
    if (tid == 0) {
        int pre = my_count < STAGES ? my_count : STAGES;
        for (int k = 0; k < pre; k++) {
            long long t = blockIdx.x + (long long)k * gridDim.x;
            uint32_t mb = smem_u32(&s_full[k]);
            mbar_expect_tx(mb, TILE_BYTES);
            bulk_g2s(smem_u32(&s_buf[k][0]), x + t * TILE_ELEMS, TILE_BYTES, mb);
        }
    }

    // ---- steady state ----
    int stg = 0, ph = 0;
    for (int k = 0; k < my_count; k++) {
        long long t = blockIdx.x + (long long)k * gridDim.x;

        mbar_wait(smem_u32(&s_full[stg]), ph);

        const float4* bin = (const float4*)&s_buf[stg][0];
        float4* o4 = (float4*)(out + t * TILE_ELEMS);
        float4 v0 = bin[tid];
        float4 v1 = bin[tid + TPB];
        lcq_vec4(v0, c, s_tab, s_lutA);  __stcs(&o4[tid], v0);
        lcq_vec4(v1, c, s_tab, s_lutA);  __stcs(&o4[tid + TPB], v1);

        mbar_arrive(smem_u32(&s_empty[stg]));

        if (tid == 0 && k + STAGES < my_count) {
            // recycle this stage: wait until ALL threads drained tile k
            mbar_wait(smem_u32(&s_empty[stg]), ph);
            long long tn = blockIdx.x + (long long)(k + STAGES) * gridDim.x;
            uint32_t mb = smem_u32(&s_full[stg]);
            mbar_expect_tx(mb, TILE_BYTES);
            bulk_g2s(smem_u32(&s_buf[stg][0]), x + tn * TILE_ELEMS, TILE_BYTES, mb);
        }

        if (++stg == STAGES) { stg = 0; ph ^= 1; }
    }

    // ---- remainder elements (n not multiple of TILE_ELEMS) ----
    if (blockIdx.x == gridDim.x - 1) {
        for (long long i = (long long)ntiles * TILE_ELEMS + tid; i < n; i += TPB)
            out[i] = lcq_elem(__ldcs(&x[i]), c, s_tab, s_lutA);
    }
}

extern "C" void kernel_launch(void* const* d_in, const int* in_sizes, int n_in,
                              void* d_out, int out_size) {
    // metadata order: x, threshold, theta, dst, Qn, Qp, num_elements
    const float* x     = (const float*)d_in[0];
    const float* thr   = (const float*)d_in[1];
    const float* theta = (const float*)d_in[2];
    const float* dst   = (const float*)d_in[3];
    const int*   qp    = (const int*)d_in[5];
    float* out = (float*)d_out;

    int n = in_sizes[0];
    int ntiles = n / TILE_ELEMS;

    int blocks = 148 * 4;               // 4 CTAs/SM (smem-limited ring depth)
    if (blocks > ntiles) blocks = ntiles;
    if (blocks < 1) blocks = 1;

    lcq_kernel<<<blocks, TPB>>>(x, thr, theta, dst, qp, out, ntiles, n);
}